// round 2
// baseline (speedup 1.0000x reference)
#include <cuda_runtime.h>

// QuantumFusionLayer reduces algebraically to:
//   out[r, k] = (1/2048) * ( sum_j (-1)^{popcount(j & k)} * combined[r, j] )^2
// i.e. per-row 2048-point Walsh-Hadamard transform, squared, scaled.
// The RZ phase is unit-modulus and cancels under |.|^2; input is real so the
// state stays real through the Hadamard ladder.

__global__ __launch_bounds__(256, 4)
void qfl_wht_kernel(const float* __restrict__ x1,
                    const float* __restrict__ x2,
                    float* __restrict__ out)
{
    __shared__ float s[2048];

    const int row  = blockIdx.x;
    const int t    = threadIdx.x;    // 0..255
    const int lane = t & 31;

    // ---- Load 8 contiguous elements of the concatenated row (coalesced .128)
    const float* src = (t < 128)
        ? (x1 + (size_t)row * 1024 + (size_t)t * 8)
        : (x2 + (size_t)row * 1024 + (size_t)(t - 128) * 8);
    float4 lo4 = __ldg((const float4*)src);
    float4 hi4 = __ldg((const float4*)src + 1);

    float v[8];
    v[0] = lo4.x; v[1] = lo4.y; v[2] = lo4.z; v[3] = lo4.w;
    v[4] = hi4.x; v[5] = hi4.y; v[6] = hi4.z; v[7] = hi4.w;

    // ---- WHT bits 0..2: in-register butterflies (element bits 0..2 = j index)
#pragma unroll
    for (int b = 0; b < 3; ++b) {
        const int m = 1 << b;
#pragma unroll
        for (int j = 0; j < 8; ++j) {
            if ((j & m) == 0) {
                float a = v[j], c = v[j | m];
                v[j]     = a + c;
                v[j | m] = a - c;
            }
        }
    }

    // ---- WHT bits 3..7: warp shuffle butterflies (lane bits = element bits 3..7)
#pragma unroll
    for (int sb = 0; sb < 5; ++sb) {
        const int m = 1 << sb;
        const bool up = (lane & m) != 0;
#pragma unroll
        for (int j = 0; j < 8; ++j) {
            float w = __shfl_xor_sync(0xffffffffu, v[j], m);
            v[j] = up ? (w - v[j]) : (v[j] + w);
        }
    }

    // ---- Stage to shared with XOR swizzle (conflict-free .128 stores AND
    //      conflict-free scalar reads at the transposed ownership below).
    // float4 index f in [0,512); swizzle fs = f ^ ((f>>3)&7).
    float4* s4 = (float4*)s;
    {
        int f0 = 2 * t;
        int f1 = 2 * t + 1;
        s4[f0 ^ ((f0 >> 3) & 7)] = make_float4(v[0], v[1], v[2], v[3]);
        s4[f1 ^ ((f1 >> 3) & 7)] = make_float4(v[4], v[5], v[6], v[7]);
    }
    __syncthreads();

    // ---- Re-own: thread t holds elements { (j<<8) | t : j=0..7 }  (bits 8..10 in regs)
    float u[8];
#pragma unroll
    for (int j = 0; j < 8; ++j) {
        int i  = (j << 8) | t;
        int f  = i >> 2;
        int fs = f ^ ((f >> 3) & 7);
        u[j] = s[fs * 4 + (i & 3)];
    }

    // ---- WHT bits 8..10: in-register butterflies on j index
#pragma unroll
    for (int b = 0; b < 3; ++b) {
        const int m = 1 << b;
#pragma unroll
        for (int j = 0; j < 8; ++j) {
            if ((j & m) == 0) {
                float a = u[j], c = u[j | m];
                u[j]     = a + c;
                u[j | m] = a - c;
            }
        }
    }

    // ---- |amp|^2 with overall scale ((1/sqrt2)^11)^2 = 2^-11; coalesced stores
    const float scale = 1.0f / 2048.0f;
    float* orow = out + (size_t)row * 2048 + t;
#pragma unroll
    for (int j = 0; j < 8; ++j) {
        orow[(size_t)(j << 8)] = u[j] * u[j] * scale;
    }
}

extern "C" void kernel_launch(void* const* d_in, const int* in_sizes, int n_in,
                              void* d_out, int out_size)
{
    const float* x1 = (const float*)d_in[0];   // (8192, 1024) f32
    const float* x2 = (const float*)d_in[1];   // (8192, 1024) f32
    float* out = (float*)d_out;                // (8192, 2048) f32

    const int rows = in_sizes[0] / 1024;       // 8192
    qfl_wht_kernel<<<rows, 256>>>(x1, x2, out);
}